// round 1
// baseline (speedup 1.0000x reference)
#include <cuda_runtime.h>

// Problem constants
#define B      32
#define T_IN   24
#define T_OUT  12
#define D      10
#define M      64
#define N      128
#define MN     (M * N)                 // 8192
#define IN_T_STRIDE  (D * MN)          // 81920 floats between t-slices
#define IN_B_STRIDE  (T_IN * IN_T_STRIDE)
#define OUT_B_STRIDE (T_OUT * MN)
#define MU     (2.0f / (T_IN + 1))     // 0.08

__global__ __launch_bounds__(256)
void movavg_kernel(const float* __restrict__ x, float* __restrict__ out)
{
    const int tid = blockIdx.x * blockDim.x + threadIdx.x;  // over B*MN
    const int b  = tid / MN;
    const int mn = tid - b * MN;

    const float* xin = x + (long long)b * IN_B_STRIDE + mn;

    // EMA coefficients (compile-time foldable):
    // base = (1-MU)^(T-1)/T ; c[j] = base + MU*(1-MU)^(T-2-j) for j<T-1 ; c[T-1]=base
    float c[T_IN];
    {
        // (1-MU)^k for k = 0..23
        float pw[T_IN];
        pw[0] = 1.0f;
        #pragma unroll
        for (int k = 1; k < T_IN; k++) pw[k] = pw[k - 1] * (1.0f - MU);
        const float base = pw[T_IN - 1] / (float)T_IN;
        #pragma unroll
        for (int j = 0; j < T_IN - 1; j++) c[j] = base + MU * pw[T_IN - 2 - j];
        c[T_IN - 1] = base;
    }

    // Load the 24-sample window (coalesced across the warp; 24-deep MLP)
    float w[T_IN];
    #pragma unroll
    for (int t = 0; t < T_IN; t++)
        w[t] = __ldg(xin + t * IN_T_STRIDE);

    float* yout = out + (long long)b * OUT_B_STRIDE + mn;

    #pragma unroll
    for (int s = 0; s < T_OUT; s++) {
        float p = 0.0f;
        #pragma unroll
        for (int t = 0; t < T_IN; t++)
            p = fmaf(w[t], c[t], p);
        // shift window, append prediction
        #pragma unroll
        for (int t = 0; t < T_IN - 1; t++) w[t] = w[t + 1];
        w[T_IN - 1] = p;
        yout[s * MN] = p;
    }
}

extern "C" void kernel_launch(void* const* d_in, const int* in_sizes, int n_in,
                              void* d_out, int out_size)
{
    const float* x = (const float*)d_in[0];
    float* out = (float*)d_out;
    const int total = B * MN;              // 262144 threads
    movavg_kernel<<<total / 256, 256>>>(x, out);
}

// round 2
// speedup vs baseline: 1.5000x; 1.5000x over previous
#include <cuda_runtime.h>

// Problem constants
#define B      32
#define T_IN   24
#define T_OUT  12
#define D      10
#define M      64
#define N      128
#define MN     (M * N)                 // 8192
#define MN4    (MN / 4)                // 2048 float4 per (b,t,d) slice row-set
#define IN_T_F4  (D * MN / 4)          // 20480 float4 stride between t slices
#define IN_B_F4  (T_IN * IN_T_F4)
#define OUT_B_F4 (T_OUT * MN4)
#define MU_    0.08f                   // 2/(T_IN+1)
#define LAM    0.92f                   // 1 - MU

__global__ __launch_bounds__(64)
void movavg_kernel(const float4* __restrict__ x, float4* __restrict__ out)
{
    const int tid = blockIdx.x * 64 + threadIdx.x;   // over B*MN/4 = 65536
    const int b   = tid >> 11;                       // / 2048
    const int mn4 = tid & 2047;

    const float4* __restrict__ xin = x + b * IN_B_F4 + mn4;

    // Compile-time constants: lam23 = LAM^23, base = lam23/24, Kc = MU*lam23
    float lam23 = 1.0f;
    #pragma unroll
    for (int i = 0; i < 23; i++) lam23 *= LAM;
    const float base = lam23 / 24.0f;
    const float Kc   = MU_ * lam23;

    // State: Bsum = window sum, R = truncated EMA (Sum MU*LAM^(22-k) * v_k),
    // v23 = newest element feeding R next step.
    float Bs[4]  = {0.f, 0.f, 0.f, 0.f};
    float R[4]   = {0.f, 0.f, 0.f, 0.f};
    float v23[4];
    float xw[T_OUT][4];   // x_0..x_11: the elements that leave the window

    #pragma unroll
    for (int t = 0; t < T_IN; t++) {
        const float4 v = __ldg(xin + t * IN_T_F4);
        const float vv[4] = {v.x, v.y, v.z, v.w};
        #pragma unroll
        for (int q = 0; q < 4; q++) {
            Bs[q] += vv[q];
            if (t < T_IN - 1) R[q] = fmaf(LAM, R[q], MU_ * vv[q]);  // Horner EMA
            if (t < T_OUT)    xw[t][q] = vv[q];
            if (t == T_IN - 1) v23[q] = vv[q];
        }
    }

    float4* __restrict__ yout = out + b * OUT_B_F4 + mn4;

    #pragma unroll
    for (int s = 0; s < T_OUT; s++) {
        float p[4];
        #pragma unroll
        for (int q = 0; q < 4; q++) {
            p[q] = fmaf(base, Bs[q], R[q]);
            // Bsum' = Bsum - x_s + p
            Bs[q] = (Bs[q] - xw[s][q]) + p[q];
            // R' = LAM*R + MU*v23 - MU*LAM^23 * x_s
            R[q] = fmaf(LAM, R[q], fmaf(MU_, v23[q], -Kc * xw[s][q]));
            v23[q] = p[q];
        }
        float4 o;
        o.x = p[0]; o.y = p[1]; o.z = p[2]; o.w = p[3];
        yout[s * MN4] = o;
    }
}

extern "C" void kernel_launch(void* const* d_in, const int* in_sizes, int n_in,
                              void* d_out, int out_size)
{
    const float4* x = (const float4*)d_in[0];
    float4* out = (float4*)d_out;
    const int total = B * MN / 4;          // 65536 threads
    movavg_kernel<<<total / 64, 64>>>(x, out);
}